// round 10
// baseline (speedup 1.0000x reference)
#include <cuda_runtime.h>
#include <mma.h>
#include <math.h>
#include <stdint.h>
#include <cstdint>

using namespace nvcuda;

// ---------------- problem constants ----------------
#define Dm   1024
#define Tn   1024
#define Bb   2
#define Hh   16
#define HDd  64
#define Ll   4
#define DFF  4096
#define VOCAB 16384
#define BT   (Bb*Tn)          // 2048 token rows

// ---------------- GEMM tile config ----------------
#define BM 128
#define BN 128
#define BK 16
#define BKP 20                // padded leading dim in smem (80B, 16B-multiple)

// ---------------- scratch (no allocations allowed) ----------------
__device__ float g_x [BT*Dm];
__device__ float g_h [BT*Dm];
__device__ float g_q [BT*Dm];
__device__ float g_k [BT*Dm];
__device__ float g_v [BT*Dm];
__device__ float g_vT[BT*Dm];                 // [B,H,HD,T]
__device__ float g_o [BT*Dm];
__device__ float g_sc[(size_t)Bb*Hh*Tn*Tn];   // 128 MB scores [B,H,T,T]
__device__ float g_g1[BT*DFF];
__device__ float g_g3[BT*DFF];
__device__ float g_cos[BT*32];
__device__ float g_sin[BT*32];

// ---------------- cp.async helpers ----------------
__device__ __forceinline__ void cp16(unsigned int dst, const float* src, bool pred)
{
    int sz = pred ? 16 : 0;
    asm volatile("cp.async.cg.shared.global [%0], [%1], 16, %2;"
                 :: "r"(dst), "l"(src), "r"(sz));
}
__device__ __forceinline__ void cp_commit()  { asm volatile("cp.async.commit_group;" ::: "memory"); }
__device__ __forceinline__ void cp_wait1()   { asm volatile("cp.async.wait_group 1;" ::: "memory"); }
__device__ __forceinline__ void cp_wait0()   { asm volatile("cp.async.wait_group 0;" ::: "memory"); }

// ---------------- 3xTF32 tensor-core batched NT GEMM: C = A[M,K] * B[N,K]^T ----------------
// Precision recovery: x = hi + lo (hi = tf32(x), lo = tf32(x - hi)), accumulate
// hi*hi + hi*lo + lo*hi in fp32. Missing lo*lo term ~2^-22 relative -> fp32-class error.
// batch z = b*Hbat + h, with separate (b,h) strides for A,B,C. beta=1 -> C += A*B^T.
// Call-site guarantees: M %128==0, K %16==0, N %16==0, all ld %4==0.
__global__ __launch_bounds__(256, 2)
void gemm_tc(const float* __restrict__ A, const float* __restrict__ B, float* __restrict__ C,
             int M, int N, int K, int lda, int ldb, int ldc,
             long long sAb, long long sAh, long long sBb, long long sBh,
             long long sCb, long long sCh, int Hbat, int beta)
{
    int z = blockIdx.z;
    int b = z / Hbat, h = z - b * Hbat;
    A += (long long)b * sAb + (long long)h * sAh;
    B += (long long)b * sBb + (long long)h * sBh;
    C += (long long)b * sCb + (long long)h * sCh;

    __shared__ float As[2][BM * BKP];
    __shared__ float Bs[2][BN * BKP];

    const int tid  = threadIdx.x;
    const int warp = tid >> 5;
    const int wm   = warp >> 2;           // 0..1 -> 64-row warp tile
    const int wn   = warp & 3;            // 0..3 -> 32-col warp tile
    const int m0   = blockIdx.y * BM;
    const int n0   = blockIdx.x * BN;

    const int lrow = tid >> 2;            // 0..63
    const int lcol = (tid & 3) * 4;       // 0,4,8,12

    unsigned int asb[2], bsb[2];
    asb[0] = (unsigned int)__cvta_generic_to_shared(&As[0][0]);
    asb[1] = (unsigned int)__cvta_generic_to_shared(&As[1][0]);
    bsb[0] = (unsigned int)__cvta_generic_to_shared(&Bs[0][0]);
    bsb[1] = (unsigned int)__cvta_generic_to_shared(&Bs[1][0]);

    wmma::fragment<wmma::accumulator, 16, 16, 8, float> acc[4][2];
#pragma unroll
    for (int i = 0; i < 4; i++)
#pragma unroll
        for (int j = 0; j < 2; j++) wmma::fill_fragment(acc[i][j], 0.0f);

    const int nt = K / BK;

    const int n1 = n0 + lrow, n2 = n0 + lrow + 64;
    const float* aBase = A + (long long)(m0 + lrow) * lda + lcol;
    const float* bBase = B + (long long)n1 * ldb + lcol;
    const long long a64 = (long long)64 * lda;
    const long long b64 = (long long)64 * ldb;
    const unsigned int aOff0 = (unsigned int)(lrow * BKP + lcol) * 4u;
    const unsigned int aOff1 = (unsigned int)((lrow + 64) * BKP + lcol) * 4u;

    // prologue: tile 0 -> buf 0
    {
        cp16(asb[0] + aOff0, aBase, true);
        cp16(asb[0] + aOff1, aBase + a64, true);
        cp16(bsb[0] + aOff0, bBase, n1 < N);
        cp16(bsb[0] + aOff1, bBase + b64, n2 < N);
        cp_commit();
    }

    for (int t = 0; t < nt; t++) {
        int cur = t & 1;
        if (t + 1 < nt) {
            int nxt = cur ^ 1;
            const float* ap = aBase + (t + 1) * BK;
            const float* bp = bBase + (t + 1) * BK;
            cp16(asb[nxt] + aOff0, ap, true);
            cp16(asb[nxt] + aOff1, ap + a64, true);
            cp16(bsb[nxt] + aOff0, bp, n1 < N);
            cp16(bsb[nxt] + aOff1, bp + b64, n2 < N);
            cp_commit();
            cp_wait1();
        } else {
            cp_wait0();
        }
        __syncthreads();

        const float* asw = &As[cur][0] + (wm * 64) * BKP;
        const float* bsw = &Bs[cur][0] + (wn * 32) * BKP;
#pragma unroll
        for (int kk = 0; kk < 2; kk++) {
            // B fragments: raw -> hi, lo (computed once per kk)
            wmma::fragment<wmma::matrix_b, 16, 16, 8, wmma::precision::tf32, wmma::col_major> bhi[2], blo[2];
#pragma unroll
            for (int j = 0; j < 2; j++) {
                wmma::load_matrix_sync(bhi[j], bsw + j * 16 * BKP + kk * 8, BKP);
#pragma unroll
                for (int e = 0; e < bhi[j].num_elements; e++) {
                    float x  = bhi[j].x[e];
                    float hi = wmma::__float_to_tf32(x);
                    bhi[j].x[e] = hi;
                    blo[j].x[e] = wmma::__float_to_tf32(x - hi);
                }
            }
            // A fragments streamed one at a time: 3 mma terms per (i,j)
#pragma unroll
            for (int i = 0; i < 4; i++) {
                wmma::fragment<wmma::matrix_a, 16, 16, 8, wmma::precision::tf32, wmma::row_major> ahi, alo;
                wmma::load_matrix_sync(ahi, asw + i * 16 * BKP + kk * 8, BKP);
#pragma unroll
                for (int e = 0; e < ahi.num_elements; e++) {
                    float x  = ahi.x[e];
                    float hi = wmma::__float_to_tf32(x);
                    ahi.x[e] = hi;
                    alo.x[e] = wmma::__float_to_tf32(x - hi);
                }
#pragma unroll
                for (int j = 0; j < 2; j++) {
                    wmma::mma_sync(acc[i][j], ahi, bhi[j], acc[i][j]);
                    wmma::mma_sync(acc[i][j], ahi, blo[j], acc[i][j]);
                    wmma::mma_sync(acc[i][j], alo, bhi[j], acc[i][j]);
                }
            }
        }
        __syncthreads();
    }

    // epilogue
#pragma unroll
    for (int i = 0; i < 4; i++) {
        int mrow = m0 + wm * 64 + i * 16;
#pragma unroll
        for (int j = 0; j < 2; j++) {
            int ncol = n0 + wn * 32 + j * 16;
            if (ncol >= N) continue;
            float* cp = C + (long long)mrow * ldc + ncol;
            if (beta) {
                wmma::fragment<wmma::accumulator, 16, 16, 8, float> cold;
                wmma::load_matrix_sync(cold, cp, ldc, wmma::mem_row_major);
#pragma unroll
                for (int e = 0; e < cold.num_elements; e++)
                    acc[i][j].x[e] += cold.x[e];
            }
            wmma::store_matrix_sync(cp, acc[i][j], ldc, wmma::mem_row_major);
        }
    }
}

// ---------------- embedding gather ----------------
__global__ __launch_bounds__(256)
void gather_k(const int* __restrict__ tok, const float* __restrict__ embed, float* __restrict__ x)
{
    int bt = blockIdx.x;
    int t = tok[bt];
    reinterpret_cast<float4*>(x + (long long)bt * Dm)[threadIdx.x] =
        reinterpret_cast<const float4*>(embed + (long long)t * Dm)[threadIdx.x];
}

// ---------------- RoPE tables (match JAX fp32 pipeline) ----------------
__global__ __launch_bounds__(256)
void rope_tables_k(const int* __restrict__ pos, float* __restrict__ cosT, float* __restrict__ sinT)
{
    int idx = blockIdx.x * blockDim.x + threadIdx.x;   // BT*32
    if (idx >= BT * 32) return;
    int i = idx & 31;
    int bt = idx >> 5;
    float t = (float)(2 * i) / 64.0f;
    float u = (float)pow(10000.0, (double)t);
    float inv = 1.0f / u;
    float ang = (float)pos[bt] * inv;
    cosT[idx] = (float)cos((double)ang);
    sinT[idx] = (float)sin((double)ang);
}

// ---------------- apply RoPE in place on q or k ----------------
__global__ __launch_bounds__(256)
void rope_apply_k(float* __restrict__ q, const float* __restrict__ cosT, const float* __restrict__ sinT)
{
    int idx = blockIdx.x * blockDim.x + threadIdx.x;   // BT*H*32
    if (idx >= BT * Hh * 32) return;
    int i  = idx & 31;
    int r  = idx >> 5;
    int hh = r & 15;
    int bt = r >> 4;
    float c = cosT[bt * 32 + i];
    float s = sinT[bt * 32 + i];
    float* p = q + (long long)bt * Dm + hh * HDd + 2 * i;
    float xr = p[0], xi = p[1];
    p[0] = xr * c - xi * s;
    p[1] = xr * s + xi * c;
}

// ---------------- RMSNorm (one block per row of 1024) ----------------
__global__ __launch_bounds__(256)
void rmsnorm_k(const float* __restrict__ x, const float* __restrict__ w, float* __restrict__ h)
{
    int row = blockIdx.x;
    float4 v = reinterpret_cast<const float4*>(x + (long long)row * Dm)[threadIdx.x];
    float ss = v.x * v.x + v.y * v.y + v.z * v.z + v.w * v.w;
#pragma unroll
    for (int o = 16; o > 0; o >>= 1) ss += __shfl_xor_sync(0xffffffffu, ss, o);
    __shared__ float red[8];
    __shared__ float rinv;
    if ((threadIdx.x & 31) == 0) red[threadIdx.x >> 5] = ss;
    __syncthreads();
    if (threadIdx.x == 0) {
        float s = 0.f;
#pragma unroll
        for (int i = 0; i < 8; i++) s += red[i];
        rinv = rsqrtf(s * (1.0f / Dm) + 1e-6f);
    }
    __syncthreads();
    float r = rinv;
    float4 wv = reinterpret_cast<const float4*>(w)[threadIdx.x];
    float4 o4 = make_float4(v.x * r * wv.x, v.y * r * wv.y, v.z * r * wv.z, v.w * r * wv.w);
    reinterpret_cast<float4*>(h + (long long)row * Dm)[threadIdx.x] = o4;
}

// ---------------- transpose v -> vT[b,h,hd,t] ----------------
__global__ __launch_bounds__(256)
void transpose_v_k(const float* __restrict__ v, float* __restrict__ vT)
{
    long long idx = (long long)blockIdx.x * blockDim.x + threadIdx.x;  // BT*Dm = 2M
    if (idx >= (long long)BT * Dm) return;
    int t  = (int)(idx & (Tn - 1));
    long long r = idx >> 10;
    int hd = (int)(r & (HDd - 1)); r >>= 6;
    int hh = (int)(r & (Hh - 1));
    int b  = (int)(r >> 4);
    vT[idx] = v[((long long)(b * Tn + t)) * Dm + hh * HDd + hd];
}

// ---------------- softmax over rows of 1024 (scale folded in) ----------------
__global__ __launch_bounds__(256)
void softmax_k(float* __restrict__ sc)
{
    long long row = blockIdx.x;
    float4* p = reinterpret_cast<float4*>(sc + row * Tn);
    int tid = threadIdx.x;
    float4 v = p[tid];
    const float scale = 0.125f;                 // 1/sqrt(64)
    v.x *= scale; v.y *= scale; v.z *= scale; v.w *= scale;
    float m = fmaxf(fmaxf(v.x, v.y), fmaxf(v.z, v.w));
#pragma unroll
    for (int o = 16; o > 0; o >>= 1) m = fmaxf(m, __shfl_xor_sync(0xffffffffu, m, o));
    __shared__ float red[8];
    __shared__ float bc;
    if ((tid & 31) == 0) red[tid >> 5] = m;
    __syncthreads();
    if (tid == 0) {
        float mm = red[0];
#pragma unroll
        for (int i = 1; i < 8; i++) mm = fmaxf(mm, red[i]);
        bc = mm;
    }
    __syncthreads();
    m = bc;
    float e0 = expf(v.x - m), e1 = expf(v.y - m), e2 = expf(v.z - m), e3 = expf(v.w - m);
    float s = e0 + e1 + e2 + e3;
#pragma unroll
    for (int o = 16; o > 0; o >>= 1) s += __shfl_xor_sync(0xffffffffu, s, o);
    __syncthreads();
    if ((tid & 31) == 0) red[tid >> 5] = s;
    __syncthreads();
    if (tid == 0) {
        float t = 0.f;
#pragma unroll
        for (int i = 0; i < 8; i++) t += red[i];
        bc = 1.0f / t;
    }
    __syncthreads();
    float inv = bc;
    p[tid] = make_float4(e0 * inv, e1 * inv, e2 * inv, e3 * inv);
}

// ---------------- g1 = silu(g1) * g3 ----------------
__global__ __launch_bounds__(256)
void silu_mul_k(float* __restrict__ g1, const float* __restrict__ g3)
{
    long long idx = (long long)blockIdx.x * blockDim.x + threadIdx.x;  // float4 count
    if (idx >= (long long)BT * DFF / 4) return;
    float4 a = reinterpret_cast<float4*>(g1)[idx];
    float4 b = reinterpret_cast<const float4*>(g3)[idx];
    a.x = (a.x / (1.f + expf(-a.x))) * b.x;
    a.y = (a.y / (1.f + expf(-a.y))) * b.y;
    a.z = (a.z / (1.f + expf(-a.z))) * b.z;
    a.w = (a.w / (1.f + expf(-a.w))) * b.w;
    reinterpret_cast<float4*>(g1)[idx] = a;
}

// ---------------- host orchestration ----------------
static inline void launch_gemm(const float* A, const float* B, float* C,
                               int M, int N, int K, int lda, int ldb, int ldc,
                               long long sAb, long long sAh, long long sBb, long long sBh,
                               long long sCb, long long sCh, int Hbat, int nbat, int beta)
{
    dim3 grid((N + BN - 1) / BN, (M + BM - 1) / BM, nbat);
    gemm_tc<<<grid, 256>>>(A, B, C, M, N, K, lda, ldb, ldc,
                           sAb, sAh, sBb, sBh, sCb, sCh, Hbat, beta);
}

extern "C" void kernel_launch(void* const* d_in, const int* in_sizes, int n_in,
                              void* d_out, int out_size)
{
    const int*   tok         = (const int*)d_in[0];
    const int*   pos         = (const int*)d_in[1];
    const float* embed       = (const float*)d_in[2];
    const float* attn_norm_w = (const float*)d_in[3];
    const float* wq          = (const float*)d_in[4];
    const float* wk          = (const float*)d_in[5];
    const float* wv          = (const float*)d_in[6];
    const float* wo          = (const float*)d_in[7];
    const float* ff_norm_w   = (const float*)d_in[8];
    const float* w1          = (const float*)d_in[9];
    const float* w2          = (const float*)d_in[10];
    const float* w3          = (const float*)d_in[11];
    const float* norm_w      = (const float*)d_in[12];
    float* out = (float*)d_out;

    float *x, *h, *q, *k, *v, *vT, *o, *sc, *g1, *g3, *ct, *st;
    cudaGetSymbolAddress((void**)&x,  g_x);
    cudaGetSymbolAddress((void**)&h,  g_h);
    cudaGetSymbolAddress((void**)&q,  g_q);
    cudaGetSymbolAddress((void**)&k,  g_k);
    cudaGetSymbolAddress((void**)&v,  g_v);
    cudaGetSymbolAddress((void**)&vT, g_vT);
    cudaGetSymbolAddress((void**)&o,  g_o);
    cudaGetSymbolAddress((void**)&sc, g_sc);
    cudaGetSymbolAddress((void**)&g1, g_g1);
    cudaGetSymbolAddress((void**)&g3, g_g3);
    cudaGetSymbolAddress((void**)&ct, g_cos);
    cudaGetSymbolAddress((void**)&st, g_sin);

    gather_k<<<BT, 256>>>(tok, embed, x);
    rope_tables_k<<<(BT * 32 + 255) / 256, 256>>>(pos, ct, st);

    const long long DD = (long long)Dm * Dm;
    for (int l = 0; l < Ll; l++) {
        // ---- attention ----
        rmsnorm_k<<<BT, 256>>>(x, attn_norm_w + (long long)l * Dm, h);
        launch_gemm(h, wq + l * DD, q, BT, Dm, Dm, Dm, Dm, Dm, 0,0,0,0,0,0, 1, 1, 0);
        launch_gemm(h, wk + l * DD, k, BT, Dm, Dm, Dm, Dm, Dm, 0,0,0,0,0,0, 1, 1, 0);
        launch_gemm(h, wv + l * DD, v, BT, Dm, Dm, Dm, Dm, Dm, 0,0,0,0,0,0, 1, 1, 0);
        rope_apply_k<<<(BT * Hh * 32 + 255) / 256, 256>>>(q, ct, st);
        rope_apply_k<<<(BT * Hh * 32 + 255) / 256, 256>>>(k, ct, st);
        transpose_v_k<<<(BT * Dm + 255) / 256, 256>>>(v, vT);
        // scores[b,h,t,s] = q . k  (batched over 32 (b,h))
        launch_gemm(q, k, sc, Tn, Tn, HDd, Dm, Dm, Tn,
                    (long long)Tn * Dm, HDd, (long long)Tn * Dm, HDd,
                    (long long)Hh * Tn * Tn, (long long)Tn * Tn, Hh, Bb * Hh, 0);
        softmax_k<<<Bb * Hh * Tn, 256>>>(sc);
        // o[b,t,h,hd] = scores . vT
        launch_gemm(sc, vT, o, Tn, HDd, Tn, Tn, Tn, Dm,
                    (long long)Hh * Tn * Tn, (long long)Tn * Tn,
                    (long long)Hh * HDd * Tn, (long long)HDd * Tn,
                    (long long)Tn * Dm, HDd, Hh, Bb * Hh, 0);
        // x += o * wo^T
        launch_gemm(o, wo + l * DD, x, BT, Dm, Dm, Dm, Dm, Dm, 0,0,0,0,0,0, 1, 1, 1);
        // ---- SwiGLU FFN ----
        rmsnorm_k<<<BT, 256>>>(x, ff_norm_w + (long long)l * Dm, h);
        launch_gemm(h, w1 + (long long)l * DFF * Dm, g1, BT, DFF, Dm, Dm, Dm, DFF, 0,0,0,0,0,0, 1, 1, 0);
        launch_gemm(h, w3 + (long long)l * DFF * Dm, g3, BT, DFF, Dm, Dm, Dm, DFF, 0,0,0,0,0,0, 1, 1, 0);
        silu_mul_k<<<(BT * DFF / 4 + 255) / 256, 256>>>(g1, g3);
        // x += g1 * w2^T  (w2 is [D, DFF])
        launch_gemm(g1, w2 + (long long)l * Dm * DFF, x, BT, Dm, DFF, DFF, DFF, Dm, 0,0,0,0,0,0, 1, 1, 1);
    }

    // ---- final norm + tied LM head ----
    rmsnorm_k<<<BT, 256>>>(x, norm_w, h);
    launch_gemm(h, embed, out, BT, VOCAB, Dm, Dm, Dm, VOCAB, 0,0,0,0,0,0, 1, 1, 0);
}

// round 11
// speedup vs baseline: 1.0638x; 1.0638x over previous
#include <cuda_runtime.h>
#include <mma.h>
#include <math.h>
#include <stdint.h>
#include <cstdint>

using namespace nvcuda;

// ---------------- problem constants ----------------
#define Dm   1024
#define Tn   1024
#define Bb   2
#define Hh   16
#define HDd  64
#define Ll   4
#define DFF  4096
#define VOCAB 16384
#define BT   (Bb*Tn)          // 2048 token rows

// ---------------- GEMM tile config ----------------
#define BM 64
#define BN 128
#define BK 16
#define BKP 20                // padded smem leading dim (80B, 16B-multiple)
#define NTHR 128              // 4 warps: 2x2 grid of 32x64 warp tiles

// ---------------- scratch (no allocations allowed) ----------------
__device__ float g_x [BT*Dm];
__device__ float g_h [BT*Dm];
__device__ float g_q [BT*Dm];
__device__ float g_k [BT*Dm];
__device__ float g_v [BT*Dm];
__device__ float g_vT[BT*Dm];                 // [B,H,HD,T]
__device__ float g_o [BT*Dm];
__device__ float g_sc[(size_t)Bb*Hh*Tn*Tn];   // 128 MB scores [B,H,T,T]
__device__ float g_g1[BT*DFF];
__device__ float g_g3[BT*DFF];
__device__ float g_cos[BT*32];
__device__ float g_sin[BT*32];

// ---------------- cp.async helpers ----------------
__device__ __forceinline__ void cp16(unsigned int dst, const float* src, bool pred)
{
    int sz = pred ? 16 : 0;
    asm volatile("cp.async.cg.shared.global [%0], [%1], 16, %2;"
                 :: "r"(dst), "l"(src), "r"(sz));
}
__device__ __forceinline__ void cp_commit()  { asm volatile("cp.async.commit_group;" ::: "memory"); }
__device__ __forceinline__ void cp_wait1()   { asm volatile("cp.async.wait_group 1;" ::: "memory"); }
__device__ __forceinline__ void cp_wait0()   { asm volatile("cp.async.wait_group 0;" ::: "memory"); }

// ---------------- 3xTF32 tensor-core batched NT GEMM: C = A[M,K] * B[N,K]^T ----------------
// Precision recovery: x = hi + lo (hi = tf32(x), lo = tf32(x - hi)); accumulate
// hi*hi + hi*lo + lo*hi in fp32 (missing lo*lo ~2^-22 relative).
// batch z = b*Hbat + h with separate (b,h) strides. beta=1 -> C += A*B^T.
// Call-site guarantees: M %64==0, K %16==0, N %16==0, ld %4==0.
__global__ __launch_bounds__(NTHR, 4)
void gemm_tc(const float* __restrict__ A, const float* __restrict__ B, float* __restrict__ C,
             int M, int N, int K, int lda, int ldb, int ldc,
             long long sAb, long long sAh, long long sBb, long long sBh,
             long long sCb, long long sCh, int Hbat, int beta)
{
    int z = blockIdx.z;
    int b = z / Hbat, h = z - b * Hbat;
    A += (long long)b * sAb + (long long)h * sAh;
    B += (long long)b * sBb + (long long)h * sBh;
    C += (long long)b * sCb + (long long)h * sCh;

    __shared__ float As[2][BM * BKP];   // 2*64*20*4  = 10.2 KB
    __shared__ float Bs[2][BN * BKP];   // 2*128*20*4 = 20.5 KB

    const int tid  = threadIdx.x;
    const int warp = tid >> 5;            // 0..3
    const int wm   = warp >> 1;           // 0..1 -> 32-row warp tile
    const int wn   = warp & 1;            // 0..1 -> 64-col warp tile
    const int m0   = blockIdx.y * BM;
    const int n0   = blockIdx.x * BN;

    // loader mapping: 128 threads, each thread owns row group (tid>>2), col (tid&3)*4
    const int lr   = tid >> 2;            // 0..31
    const int lc   = (tid & 3) * 4;       // 0,4,8,12

    unsigned int asb[2], bsb[2];
    asb[0] = (unsigned int)__cvta_generic_to_shared(&As[0][0]);
    asb[1] = (unsigned int)__cvta_generic_to_shared(&As[1][0]);
    bsb[0] = (unsigned int)__cvta_generic_to_shared(&Bs[0][0]);
    bsb[1] = (unsigned int)__cvta_generic_to_shared(&Bs[1][0]);

    wmma::fragment<wmma::accumulator, 16, 16, 8, float> acc[2][4];
#pragma unroll
    for (int i = 0; i < 2; i++)
#pragma unroll
        for (int j = 0; j < 4; j++) wmma::fill_fragment(acc[i][j], 0.0f);

    const int nt = K / BK;

    // A: rows lr, lr+32 (2 cp16); B: rows lr, +32, +64, +96 (4 cp16)
    const float* aBase = A + (long long)(m0 + lr) * lda + lc;
    const float* bBase = B + (long long)(n0 + lr) * ldb + lc;
    const long long a32 = (long long)32 * lda;
    const long long b32 = (long long)32 * ldb;
    const bool bp0 = (n0 + lr)      < N;
    const bool bp1 = (n0 + lr + 32) < N;
    const bool bp2 = (n0 + lr + 64) < N;
    const bool bp3 = (n0 + lr + 96) < N;
    const unsigned int sA0 = (unsigned int)(lr * BKP + lc) * 4u;
    const unsigned int sA1 = (unsigned int)((lr + 32) * BKP + lc) * 4u;
    const unsigned int sB2 = (unsigned int)((lr + 64) * BKP + lc) * 4u;
    const unsigned int sB3 = (unsigned int)((lr + 96) * BKP + lc) * 4u;

    // per-warp compute guard (AV gemm has N=64 -> wn=1 warps have no valid cols)
    const bool active = (n0 + wn * 64) < N;

    // prologue: tile 0 -> buf 0
    {
        cp16(asb[0] + sA0, aBase, true);
        cp16(asb[0] + sA1, aBase + a32, true);
        cp16(bsb[0] + sA0, bBase, bp0);
        cp16(bsb[0] + sA1, bBase + b32, bp1);
        cp16(bsb[0] + sB2, bBase + 2 * b32, bp2);
        cp16(bsb[0] + sB3, bBase + 3 * b32, bp3);
        cp_commit();
    }

    for (int t = 0; t < nt; t++) {
        int cur = t & 1;
        if (t + 1 < nt) {
            int nxt = cur ^ 1;
            const float* ap = aBase + (t + 1) * BK;
            const float* bp = bBase + (t + 1) * BK;
            cp16(asb[nxt] + sA0, ap, true);
            cp16(asb[nxt] + sA1, ap + a32, true);
            cp16(bsb[nxt] + sA0, bp, bp0);
            cp16(bsb[nxt] + sA1, bp + b32, bp1);
            cp16(bsb[nxt] + sB2, bp + 2 * b32, bp2);
            cp16(bsb[nxt] + sB3, bp + 3 * b32, bp3);
            cp_commit();
            cp_wait1();
        } else {
            cp_wait0();
        }
        __syncthreads();

        if (active) {
            const float* asw = &As[cur][0] + (wm * 32) * BKP;
            const float* bsw = &Bs[cur][0] + (wn * 64) * BKP;
#pragma unroll
            for (int kk = 0; kk < 2; kk++) {
                // B fragments: raw -> hi, lo (once per kk)
                wmma::fragment<wmma::matrix_b, 16, 16, 8, wmma::precision::tf32, wmma::col_major> bhi[4], blo[4];
#pragma unroll
                for (int j = 0; j < 4; j++) {
                    wmma::load_matrix_sync(bhi[j], bsw + j * 16 * BKP + kk * 8, BKP);
#pragma unroll
                    for (int e = 0; e < bhi[j].num_elements; e++) {
                        float x  = bhi[j].x[e];
                        float hi = wmma::__float_to_tf32(x);
                        bhi[j].x[e] = hi;
                        blo[j].x[e] = wmma::__float_to_tf32(x - hi);
                    }
                }
                // A fragments streamed: 3 mma terms per (i,j)
#pragma unroll
                for (int i = 0; i < 2; i++) {
                    wmma::fragment<wmma::matrix_a, 16, 16, 8, wmma::precision::tf32, wmma::row_major> ahi, alo;
                    wmma::load_matrix_sync(ahi, asw + i * 16 * BKP + kk * 8, BKP);
#pragma unroll
                    for (int e = 0; e < ahi.num_elements; e++) {
                        float x  = ahi.x[e];
                        float hi = wmma::__float_to_tf32(x);
                        ahi.x[e] = hi;
                        alo.x[e] = wmma::__float_to_tf32(x - hi);
                    }
#pragma unroll
                    for (int j = 0; j < 4; j++) {
                        wmma::mma_sync(acc[i][j], ahi, bhi[j], acc[i][j]);
                        wmma::mma_sync(acc[i][j], ahi, blo[j], acc[i][j]);
                        wmma::mma_sync(acc[i][j], alo, bhi[j], acc[i][j]);
                    }
                }
            }
        }
        __syncthreads();
    }

    // epilogue
    if (active) {
#pragma unroll
        for (int i = 0; i < 2; i++) {
            int mrow = m0 + wm * 32 + i * 16;
#pragma unroll
            for (int j = 0; j < 4; j++) {
                int ncol = n0 + wn * 64 + j * 16;
                if (ncol >= N) continue;
                float* cp = C + (long long)mrow * ldc + ncol;
                if (beta) {
                    wmma::fragment<wmma::accumulator, 16, 16, 8, float> cold;
                    wmma::load_matrix_sync(cold, cp, ldc, wmma::mem_row_major);
#pragma unroll
                    for (int e = 0; e < cold.num_elements; e++)
                        acc[i][j].x[e] += cold.x[e];
                }
                wmma::store_matrix_sync(cp, acc[i][j], ldc, wmma::mem_row_major);
            }
        }
    }
}

// ---------------- embedding gather ----------------
__global__ __launch_bounds__(256)
void gather_k(const int* __restrict__ tok, const float* __restrict__ embed, float* __restrict__ x)
{
    int bt = blockIdx.x;
    int t = tok[bt];
    reinterpret_cast<float4*>(x + (long long)bt * Dm)[threadIdx.x] =
        reinterpret_cast<const float4*>(embed + (long long)t * Dm)[threadIdx.x];
}

// ---------------- RoPE tables (match JAX fp32 pipeline) ----------------
__global__ __launch_bounds__(256)
void rope_tables_k(const int* __restrict__ pos, float* __restrict__ cosT, float* __restrict__ sinT)
{
    int idx = blockIdx.x * blockDim.x + threadIdx.x;   // BT*32
    if (idx >= BT * 32) return;
    int i = idx & 31;
    int bt = idx >> 5;
    float t = (float)(2 * i) / 64.0f;
    float u = (float)pow(10000.0, (double)t);
    float inv = 1.0f / u;
    float ang = (float)pos[bt] * inv;
    cosT[idx] = (float)cos((double)ang);
    sinT[idx] = (float)sin((double)ang);
}

// ---------------- apply RoPE in place on q or k ----------------
__global__ __launch_bounds__(256)
void rope_apply_k(float* __restrict__ q, const float* __restrict__ cosT, const float* __restrict__ sinT)
{
    int idx = blockIdx.x * blockDim.x + threadIdx.x;   // BT*H*32
    if (idx >= BT * Hh * 32) return;
    int i  = idx & 31;
    int r  = idx >> 5;
    int hh = r & 15;
    int bt = r >> 4;
    float c = cosT[bt * 32 + i];
    float s = sinT[bt * 32 + i];
    float* p = q + (long long)bt * Dm + hh * HDd + 2 * i;
    float xr = p[0], xi = p[1];
    p[0] = xr * c - xi * s;
    p[1] = xr * s + xi * c;
}

// ---------------- RMSNorm (one block per row of 1024) ----------------
__global__ __launch_bounds__(256)
void rmsnorm_k(const float* __restrict__ x, const float* __restrict__ w, float* __restrict__ h)
{
    int row = blockIdx.x;
    float4 v = reinterpret_cast<const float4*>(x + (long long)row * Dm)[threadIdx.x];
    float ss = v.x * v.x + v.y * v.y + v.z * v.z + v.w * v.w;
#pragma unroll
    for (int o = 16; o > 0; o >>= 1) ss += __shfl_xor_sync(0xffffffffu, ss, o);
    __shared__ float red[8];
    __shared__ float rinv;
    if ((threadIdx.x & 31) == 0) red[threadIdx.x >> 5] = ss;
    __syncthreads();
    if (threadIdx.x == 0) {
        float s = 0.f;
#pragma unroll
        for (int i = 0; i < 8; i++) s += red[i];
        rinv = rsqrtf(s * (1.0f / Dm) + 1e-6f);
    }
    __syncthreads();
    float r = rinv;
    float4 wv = reinterpret_cast<const float4*>(w)[threadIdx.x];
    float4 o4 = make_float4(v.x * r * wv.x, v.y * r * wv.y, v.z * r * wv.z, v.w * r * wv.w);
    reinterpret_cast<float4*>(h + (long long)row * Dm)[threadIdx.x] = o4;
}

// ---------------- transpose v -> vT[b,h,hd,t] ----------------
__global__ __launch_bounds__(256)
void transpose_v_k(const float* __restrict__ v, float* __restrict__ vT)
{
    long long idx = (long long)blockIdx.x * blockDim.x + threadIdx.x;  // BT*Dm = 2M
    if (idx >= (long long)BT * Dm) return;
    int t  = (int)(idx & (Tn - 1));
    long long r = idx >> 10;
    int hd = (int)(r & (HDd - 1)); r >>= 6;
    int hh = (int)(r & (Hh - 1));
    int b  = (int)(r >> 4);
    vT[idx] = v[((long long)(b * Tn + t)) * Dm + hh * HDd + hd];
}

// ---------------- softmax over rows of 1024 (scale folded in) ----------------
__global__ __launch_bounds__(256)
void softmax_k(float* __restrict__ sc)
{
    long long row = blockIdx.x;
    float4* p = reinterpret_cast<float4*>(sc + row * Tn);
    int tid = threadIdx.x;
    float4 v = p[tid];
    const float scale = 0.125f;                 // 1/sqrt(64)
    v.x *= scale; v.y *= scale; v.z *= scale; v.w *= scale;
    float m = fmaxf(fmaxf(v.x, v.y), fmaxf(v.z, v.w));
#pragma unroll
    for (int o = 16; o > 0; o >>= 1) m = fmaxf(m, __shfl_xor_sync(0xffffffffu, m, o));
    __shared__ float red[8];
    __shared__ float bc;
    if ((tid & 31) == 0) red[tid >> 5] = m;
    __syncthreads();
    if (tid == 0) {
        float mm = red[0];
#pragma unroll
        for (int i = 1; i < 8; i++) mm = fmaxf(mm, red[i]);
        bc = mm;
    }
    __syncthreads();
    m = bc;
    float e0 = expf(v.x - m), e1 = expf(v.y - m), e2 = expf(v.z - m), e3 = expf(v.w - m);
    float s = e0 + e1 + e2 + e3;
#pragma unroll
    for (int o = 16; o > 0; o >>= 1) s += __shfl_xor_sync(0xffffffffu, s, o);
    __syncthreads();
    if ((tid & 31) == 0) red[tid >> 5] = s;
    __syncthreads();
    if (tid == 0) {
        float t = 0.f;
#pragma unroll
        for (int i = 0; i < 8; i++) t += red[i];
        bc = 1.0f / t;
    }
    __syncthreads();
    float inv = bc;
    p[tid] = make_float4(e0 * inv, e1 * inv, e2 * inv, e3 * inv);
}

// ---------------- g1 = silu(g1) * g3 ----------------
__global__ __launch_bounds__(256)
void silu_mul_k(float* __restrict__ g1, const float* __restrict__ g3)
{
    long long idx = (long long)blockIdx.x * blockDim.x + threadIdx.x;  // float4 count
    if (idx >= (long long)BT * DFF / 4) return;
    float4 a = reinterpret_cast<float4*>(g1)[idx];
    float4 b = reinterpret_cast<const float4*>(g3)[idx];
    a.x = (a.x / (1.f + expf(-a.x))) * b.x;
    a.y = (a.y / (1.f + expf(-a.y))) * b.y;
    a.z = (a.z / (1.f + expf(-a.z))) * b.z;
    a.w = (a.w / (1.f + expf(-a.w))) * b.w;
    reinterpret_cast<float4*>(g1)[idx] = a;
}

// ---------------- host orchestration ----------------
static inline void launch_gemm(const float* A, const float* B, float* C,
                               int M, int N, int K, int lda, int ldb, int ldc,
                               long long sAb, long long sAh, long long sBb, long long sBh,
                               long long sCb, long long sCh, int Hbat, int nbat, int beta)
{
    dim3 grid((N + BN - 1) / BN, (M + BM - 1) / BM, nbat);
    gemm_tc<<<grid, NTHR>>>(A, B, C, M, N, K, lda, ldb, ldc,
                            sAb, sAh, sBb, sBh, sCb, sCh, Hbat, beta);
}

extern "C" void kernel_launch(void* const* d_in, const int* in_sizes, int n_in,
                              void* d_out, int out_size)
{
    const int*   tok         = (const int*)d_in[0];
    const int*   pos         = (const int*)d_in[1];
    const float* embed       = (const float*)d_in[2];
    const float* attn_norm_w = (const float*)d_in[3];
    const float* wq          = (const float*)d_in[4];
    const float* wk          = (const float*)d_in[5];
    const float* wv          = (const float*)d_in[6];
    const float* wo          = (const float*)d_in[7];
    const float* ff_norm_w   = (const float*)d_in[8];
    const float* w1          = (const float*)d_in[9];
    const float* w2          = (const float*)d_in[10];
    const float* w3          = (const float*)d_in[11];
    const float* norm_w      = (const float*)d_in[12];
    float* out = (float*)d_out;

    float *x, *h, *q, *k, *v, *vT, *o, *sc, *g1, *g3, *ct, *st;
    cudaGetSymbolAddress((void**)&x,  g_x);
    cudaGetSymbolAddress((void**)&h,  g_h);
    cudaGetSymbolAddress((void**)&q,  g_q);
    cudaGetSymbolAddress((void**)&k,  g_k);
    cudaGetSymbolAddress((void**)&v,  g_v);
    cudaGetSymbolAddress((void**)&vT, g_vT);
    cudaGetSymbolAddress((void**)&o,  g_o);
    cudaGetSymbolAddress((void**)&sc, g_sc);
    cudaGetSymbolAddress((void**)&g1, g_g1);
    cudaGetSymbolAddress((void**)&g3, g_g3);
    cudaGetSymbolAddress((void**)&ct, g_cos);
    cudaGetSymbolAddress((void**)&st, g_sin);

    gather_k<<<BT, 256>>>(tok, embed, x);
    rope_tables_k<<<(BT * 32 + 255) / 256, 256>>>(pos, ct, st);

    const long long DD = (long long)Dm * Dm;
    for (int l = 0; l < Ll; l++) {
        // ---- attention ----
        rmsnorm_k<<<BT, 256>>>(x, attn_norm_w + (long long)l * Dm, h);
        launch_gemm(h, wq + l * DD, q, BT, Dm, Dm, Dm, Dm, Dm, 0,0,0,0,0,0, 1, 1, 0);
        launch_gemm(h, wk + l * DD, k, BT, Dm, Dm, Dm, Dm, Dm, 0,0,0,0,0,0, 1, 1, 0);
        launch_gemm(h, wv + l * DD, v, BT, Dm, Dm, Dm, Dm, Dm, 0,0,0,0,0,0, 1, 1, 0);
        rope_apply_k<<<(BT * Hh * 32 + 255) / 256, 256>>>(q, ct, st);
        rope_apply_k<<<(BT * Hh * 32 + 255) / 256, 256>>>(k, ct, st);
        transpose_v_k<<<(BT * Dm + 255) / 256, 256>>>(v, vT);
        // scores[b,h,t,s] = q . k  (batched over 32 (b,h))
        launch_gemm(q, k, sc, Tn, Tn, HDd, Dm, Dm, Tn,
                    (long long)Tn * Dm, HDd, (long long)Tn * Dm, HDd,
                    (long long)Hh * Tn * Tn, (long long)Tn * Tn, Hh, Bb * Hh, 0);
        softmax_k<<<Bb * Hh * Tn, 256>>>(sc);
        // o[b,t,h,hd] = scores . vT
        launch_gemm(sc, vT, o, Tn, HDd, Tn, Tn, Tn, Dm,
                    (long long)Hh * Tn * Tn, (long long)Tn * Tn,
                    (long long)Hh * HDd * Tn, (long long)HDd * Tn,
                    (long long)Tn * Dm, HDd, Hh, Bb * Hh, 0);
        // x += o * wo^T
        launch_gemm(o, wo + l * DD, x, BT, Dm, Dm, Dm, Dm, Dm, 0,0,0,0,0,0, 1, 1, 1);
        // ---- SwiGLU FFN ----
        rmsnorm_k<<<BT, 256>>>(x, ff_norm_w + (long long)l * Dm, h);
        launch_gemm(h, w1 + (long long)l * DFF * Dm, g1, BT, DFF, Dm, Dm, Dm, DFF, 0,0,0,0,0,0, 1, 1, 0);
        launch_gemm(h, w3 + (long long)l * DFF * Dm, g3, BT, DFF, Dm, Dm, Dm, DFF, 0,0,0,0,0,0, 1, 1, 0);
        silu_mul_k<<<(BT * DFF / 4 + 255) / 256, 256>>>(g1, g3);
        // x += g1 * w2^T  (w2 is [D, DFF])
        launch_gemm(g1, w2 + (long long)l * Dm * DFF, x, BT, Dm, DFF, DFF, DFF, Dm, 0,0,0,0,0,0, 1, 1, 1);
    }

    // ---- final norm + tied LM head ----
    rmsnorm_k<<<BT, 256>>>(x, norm_w, h);
    launch_gemm(h, embed, out, BT, VOCAB, Dm, Dm, Dm, VOCAB, 0,0,0,0,0,0, 1, 1, 0);
}

// round 12
// speedup vs baseline: 1.1223x; 1.0550x over previous
#include <cuda_runtime.h>
#include <mma.h>
#include <math.h>
#include <stdint.h>
#include <cstdint>

using namespace nvcuda;

// ---------------- problem constants ----------------
#define Dm   1024
#define Tn   1024
#define Bb   2
#define Hh   16
#define HDd  64
#define Ll   4
#define DFF  4096
#define VOCAB 16384
#define BT   (Bb*Tn)          // 2048 token rows
#define SPCAP ((long long)BT*Dm)   // one split-partial slab (2M floats)

// ---------------- GEMM tile config ----------------
#define BM 64
#define BN 128
#define BK 16
#define BKP 20                // padded smem leading dim (80B, 16B-multiple)
#define NTHR 128              // 4 warps: 2x2 grid of 32x64 warp tiles

// ---------------- scratch (no allocations allowed) ----------------
__device__ float g_x [BT*Dm];
__device__ float g_h [BT*Dm];
__device__ float g_q [BT*Dm];
__device__ float g_k [BT*Dm];
__device__ float g_v [BT*Dm];
__device__ float g_vT[BT*Dm];                 // [B,H,HD,T]
__device__ float g_o [BT*Dm];
__device__ float g_sc[(size_t)Bb*Hh*Tn*Tn];   // 128 MB scores [B,H,T,T]
__device__ float g_g1[BT*DFF];
__device__ float g_g3[BT*DFF];
__device__ float g_cos[BT*32];
__device__ float g_sin[BT*32];
__device__ float g_sp[3][BT*Dm];              // split-K partial slabs (splits 1..3)

// ---------------- cp.async helpers ----------------
__device__ __forceinline__ void cp16(unsigned int dst, const float* src, bool pred)
{
    int sz = pred ? 16 : 0;
    asm volatile("cp.async.cg.shared.global [%0], [%1], 16, %2;"
                 :: "r"(dst), "l"(src), "r"(sz));
}
__device__ __forceinline__ void cp_commit()  { asm volatile("cp.async.commit_group;" ::: "memory"); }
__device__ __forceinline__ void cp_wait1()   { asm volatile("cp.async.wait_group 1;" ::: "memory"); }
__device__ __forceinline__ void cp_wait0()   { asm volatile("cp.async.wait_group 0;" ::: "memory"); }

// ---------------- 3xTF32 tensor-core batched NT GEMM with in-launch split-K ----------
// C = A[M,K] * B[N,K]^T.  grid.z = splitS * nbatTot; z = split*nbatTot + (b*Hbat+h).
// Split 0 writes C (honoring beta); split s>0 overwrites slab spBase + (s-1)*SPCAP
// using identical addressing. A reduce kernel then adds the slabs into C.
// Call-site guarantees: M %64==0, Keff %16==0, N %16==0, ld %4==0.
__global__ __launch_bounds__(NTHR, 4)
void gemm_tc(const float* __restrict__ A, const float* __restrict__ B, float* __restrict__ C,
             int M, int N, int K, int lda, int ldb, int ldc,
             long long sAb, long long sAh, long long sBb, long long sBh,
             long long sCb, long long sCh, int Hbat, int beta,
             int nbatTot, int splitS, float* __restrict__ spBase)
{
    int zz = blockIdx.z;
    int split = zz / nbatTot;
    int zb    = zz - split * nbatTot;
    int b = zb / Hbat, h = zb - b * Hbat;

    const int Keff = K / splitS;
    const int kOff = split * Keff;

    A += (long long)b * sAb + (long long)h * sAh + kOff;
    B += (long long)b * sBb + (long long)h * sBh + kOff;
    const long long cOff = (long long)b * sCb + (long long)h * sCh;
    float* Cout = (split == 0) ? (C + cOff)
                               : (spBase + (long long)(split - 1) * SPCAP + cOff);
    const int useBeta = (split == 0) ? beta : 0;

    __shared__ float As[2][BM * BKP];   // 10.2 KB
    __shared__ float Bs[2][BN * BKP];   // 20.5 KB

    const int tid  = threadIdx.x;
    const int warp = tid >> 5;            // 0..3
    const int wm   = warp >> 1;           // 0..1 -> 32-row warp tile
    const int wn   = warp & 1;            // 0..1 -> 64-col warp tile
    const int m0   = blockIdx.y * BM;
    const int n0   = blockIdx.x * BN;

    const int lr   = tid >> 2;            // 0..31
    const int lc   = (tid & 3) * 4;       // 0,4,8,12

    unsigned int asb[2], bsb[2];
    asb[0] = (unsigned int)__cvta_generic_to_shared(&As[0][0]);
    asb[1] = (unsigned int)__cvta_generic_to_shared(&As[1][0]);
    bsb[0] = (unsigned int)__cvta_generic_to_shared(&Bs[0][0]);
    bsb[1] = (unsigned int)__cvta_generic_to_shared(&Bs[1][0]);

    wmma::fragment<wmma::accumulator, 16, 16, 8, float> acc[2][4];
#pragma unroll
    for (int i = 0; i < 2; i++)
#pragma unroll
        for (int j = 0; j < 4; j++) wmma::fill_fragment(acc[i][j], 0.0f);

    const int nt = Keff / BK;

    const float* aBase = A + (long long)(m0 + lr) * lda + lc;
    const float* bBase = B + (long long)(n0 + lr) * ldb + lc;
    const long long a32 = (long long)32 * lda;
    const long long b32 = (long long)32 * ldb;
    const bool bp0 = (n0 + lr)      < N;
    const bool bp1 = (n0 + lr + 32) < N;
    const bool bp2 = (n0 + lr + 64) < N;
    const bool bp3 = (n0 + lr + 96) < N;
    const unsigned int sA0 = (unsigned int)(lr * BKP + lc) * 4u;
    const unsigned int sA1 = (unsigned int)((lr + 32) * BKP + lc) * 4u;
    const unsigned int sB2 = (unsigned int)((lr + 64) * BKP + lc) * 4u;
    const unsigned int sB3 = (unsigned int)((lr + 96) * BKP + lc) * 4u;

    // per-warp compute guard (AV gemm has N=64 -> wn=1 warps have no valid cols)
    const bool active = (n0 + wn * 64) < N;

    // prologue: tile 0 -> buf 0
    {
        cp16(asb[0] + sA0, aBase, true);
        cp16(asb[0] + sA1, aBase + a32, true);
        cp16(bsb[0] + sA0, bBase, bp0);
        cp16(bsb[0] + sA1, bBase + b32, bp1);
        cp16(bsb[0] + sB2, bBase + 2 * b32, bp2);
        cp16(bsb[0] + sB3, bBase + 3 * b32, bp3);
        cp_commit();
    }

    for (int t = 0; t < nt; t++) {
        int cur = t & 1;
        if (t + 1 < nt) {
            int nxt = cur ^ 1;
            const float* ap = aBase + (t + 1) * BK;
            const float* bp = bBase + (t + 1) * BK;
            cp16(asb[nxt] + sA0, ap, true);
            cp16(asb[nxt] + sA1, ap + a32, true);
            cp16(bsb[nxt] + sA0, bp, bp0);
            cp16(bsb[nxt] + sA1, bp + b32, bp1);
            cp16(bsb[nxt] + sB2, bp + 2 * b32, bp2);
            cp16(bsb[nxt] + sB3, bp + 3 * b32, bp3);
            cp_commit();
            cp_wait1();
        } else {
            cp_wait0();
        }
        __syncthreads();

        if (active) {
            const float* asw = &As[cur][0] + (wm * 32) * BKP;
            const float* bsw = &Bs[cur][0] + (wn * 64) * BKP;
#pragma unroll
            for (int kk = 0; kk < 2; kk++) {
                wmma::fragment<wmma::matrix_b, 16, 16, 8, wmma::precision::tf32, wmma::col_major> bhi[4], blo[4];
#pragma unroll
                for (int j = 0; j < 4; j++) {
                    wmma::load_matrix_sync(bhi[j], bsw + j * 16 * BKP + kk * 8, BKP);
#pragma unroll
                    for (int e = 0; e < bhi[j].num_elements; e++) {
                        float x  = bhi[j].x[e];
                        float hi = wmma::__float_to_tf32(x);
                        bhi[j].x[e] = hi;
                        blo[j].x[e] = wmma::__float_to_tf32(x - hi);
                    }
                }
#pragma unroll
                for (int i = 0; i < 2; i++) {
                    wmma::fragment<wmma::matrix_a, 16, 16, 8, wmma::precision::tf32, wmma::row_major> ahi, alo;
                    wmma::load_matrix_sync(ahi, asw + i * 16 * BKP + kk * 8, BKP);
#pragma unroll
                    for (int e = 0; e < ahi.num_elements; e++) {
                        float x  = ahi.x[e];
                        float hi = wmma::__float_to_tf32(x);
                        ahi.x[e] = hi;
                        alo.x[e] = wmma::__float_to_tf32(x - hi);
                    }
#pragma unroll
                    for (int j = 0; j < 4; j++) {
                        wmma::mma_sync(acc[i][j], ahi, bhi[j], acc[i][j]);
                        wmma::mma_sync(acc[i][j], ahi, blo[j], acc[i][j]);
                        wmma::mma_sync(acc[i][j], alo, bhi[j], acc[i][j]);
                    }
                }
            }
        }
        __syncthreads();
    }

    // epilogue
    if (active) {
#pragma unroll
        for (int i = 0; i < 2; i++) {
            int mrow = m0 + wm * 32 + i * 16;
#pragma unroll
            for (int j = 0; j < 4; j++) {
                int ncol = n0 + wn * 64 + j * 16;
                if (ncol >= N) continue;
                float* cp = Cout + (long long)mrow * ldc + ncol;
                if (useBeta) {
                    wmma::fragment<wmma::accumulator, 16, 16, 8, float> cold;
                    wmma::load_matrix_sync(cold, cp, ldc, wmma::mem_row_major);
#pragma unroll
                    for (int e = 0; e < cold.num_elements; e++)
                        acc[i][j].x[e] += cold.x[e];
                }
                wmma::store_matrix_sync(cp, acc[i][j], ldc, wmma::mem_row_major);
            }
        }
    }
}

// ---------------- split-K reduce: C[i] += sum_s sp[s][i], fixed order ----------------
__global__ __launch_bounds__(256)
void reduce_k(float* __restrict__ C, const float* __restrict__ sp, int nSlabs)
{
    long long idx = (long long)blockIdx.x * blockDim.x + threadIdx.x;  // float4 index
    if (idx >= SPCAP / 4) return;
    float4 c = reinterpret_cast<float4*>(C)[idx];
#pragma unroll 3
    for (int s = 0; s < nSlabs; s++) {
        float4 p = reinterpret_cast<const float4*>(sp + (long long)s * SPCAP)[idx];
        c.x += p.x; c.y += p.y; c.z += p.z; c.w += p.w;
    }
    reinterpret_cast<float4*>(C)[idx] = c;
}

// ---------------- embedding gather ----------------
__global__ __launch_bounds__(256)
void gather_k(const int* __restrict__ tok, const float* __restrict__ embed, float* __restrict__ x)
{
    int bt = blockIdx.x;
    int t = tok[bt];
    reinterpret_cast<float4*>(x + (long long)bt * Dm)[threadIdx.x] =
        reinterpret_cast<const float4*>(embed + (long long)t * Dm)[threadIdx.x];
}

// ---------------- RoPE tables (match JAX fp32 pipeline) ----------------
__global__ __launch_bounds__(256)
void rope_tables_k(const int* __restrict__ pos, float* __restrict__ cosT, float* __restrict__ sinT)
{
    int idx = blockIdx.x * blockDim.x + threadIdx.x;   // BT*32
    if (idx >= BT * 32) return;
    int i = idx & 31;
    int bt = idx >> 5;
    float t = (float)(2 * i) / 64.0f;
    float u = (float)pow(10000.0, (double)t);
    float inv = 1.0f / u;
    float ang = (float)pos[bt] * inv;
    cosT[idx] = (float)cos((double)ang);
    sinT[idx] = (float)sin((double)ang);
}

// ---------------- apply RoPE in place on q or k ----------------
__global__ __launch_bounds__(256)
void rope_apply_k(float* __restrict__ q, const float* __restrict__ cosT, const float* __restrict__ sinT)
{
    int idx = blockIdx.x * blockDim.x + threadIdx.x;   // BT*H*32
    if (idx >= BT * Hh * 32) return;
    int i  = idx & 31;
    int r  = idx >> 5;
    int hh = r & 15;
    int bt = r >> 4;
    float c = cosT[bt * 32 + i];
    float s = sinT[bt * 32 + i];
    float* p = q + (long long)bt * Dm + hh * HDd + 2 * i;
    float xr = p[0], xi = p[1];
    p[0] = xr * c - xi * s;
    p[1] = xr * s + xi * c;
}

// ---------------- RMSNorm (one block per row of 1024) ----------------
__global__ __launch_bounds__(256)
void rmsnorm_k(const float* __restrict__ x, const float* __restrict__ w, float* __restrict__ h)
{
    int row = blockIdx.x;
    float4 v = reinterpret_cast<const float4*>(x + (long long)row * Dm)[threadIdx.x];
    float ss = v.x * v.x + v.y * v.y + v.z * v.z + v.w * v.w;
#pragma unroll
    for (int o = 16; o > 0; o >>= 1) ss += __shfl_xor_sync(0xffffffffu, ss, o);
    __shared__ float red[8];
    __shared__ float rinv;
    if ((threadIdx.x & 31) == 0) red[threadIdx.x >> 5] = ss;
    __syncthreads();
    if (threadIdx.x == 0) {
        float s = 0.f;
#pragma unroll
        for (int i = 0; i < 8; i++) s += red[i];
        rinv = rsqrtf(s * (1.0f / Dm) + 1e-6f);
    }
    __syncthreads();
    float r = rinv;
    float4 wv = reinterpret_cast<const float4*>(w)[threadIdx.x];
    float4 o4 = make_float4(v.x * r * wv.x, v.y * r * wv.y, v.z * r * wv.z, v.w * r * wv.w);
    reinterpret_cast<float4*>(h + (long long)row * Dm)[threadIdx.x] = o4;
}

// ---------------- transpose v -> vT[b,h,hd,t] ----------------
__global__ __launch_bounds__(256)
void transpose_v_k(const float* __restrict__ v, float* __restrict__ vT)
{
    long long idx = (long long)blockIdx.x * blockDim.x + threadIdx.x;  // BT*Dm = 2M
    if (idx >= (long long)BT * Dm) return;
    int t  = (int)(idx & (Tn - 1));
    long long r = idx >> 10;
    int hd = (int)(r & (HDd - 1)); r >>= 6;
    int hh = (int)(r & (Hh - 1));
    int b  = (int)(r >> 4);
    vT[idx] = v[((long long)(b * Tn + t)) * Dm + hh * HDd + hd];
}

// ---------------- softmax over rows of 1024 (scale folded in) ----------------
__global__ __launch_bounds__(256)
void softmax_k(float* __restrict__ sc)
{
    long long row = blockIdx.x;
    float4* p = reinterpret_cast<float4*>(sc + row * Tn);
    int tid = threadIdx.x;
    float4 v = p[tid];
    const float scale = 0.125f;                 // 1/sqrt(64)
    v.x *= scale; v.y *= scale; v.z *= scale; v.w *= scale;
    float m = fmaxf(fmaxf(v.x, v.y), fmaxf(v.z, v.w));
#pragma unroll
    for (int o = 16; o > 0; o >>= 1) m = fmaxf(m, __shfl_xor_sync(0xffffffffu, m, o));
    __shared__ float red[8];
    __shared__ float bc;
    if ((tid & 31) == 0) red[tid >> 5] = m;
    __syncthreads();
    if (tid == 0) {
        float mm = red[0];
#pragma unroll
        for (int i = 1; i < 8; i++) mm = fmaxf(mm, red[i]);
        bc = mm;
    }
    __syncthreads();
    m = bc;
    float e0 = expf(v.x - m), e1 = expf(v.y - m), e2 = expf(v.z - m), e3 = expf(v.w - m);
    float s = e0 + e1 + e2 + e3;
#pragma unroll
    for (int o = 16; o > 0; o >>= 1) s += __shfl_xor_sync(0xffffffffu, s, o);
    __syncthreads();
    if ((tid & 31) == 0) red[tid >> 5] = s;
    __syncthreads();
    if (tid == 0) {
        float t = 0.f;
#pragma unroll
        for (int i = 0; i < 8; i++) t += red[i];
        bc = 1.0f / t;
    }
    __syncthreads();
    float inv = bc;
    p[tid] = make_float4(e0 * inv, e1 * inv, e2 * inv, e3 * inv);
}

// ---------------- g1 = silu(g1) * g3 ----------------
__global__ __launch_bounds__(256)
void silu_mul_k(float* __restrict__ g1, const float* __restrict__ g3)
{
    long long idx = (long long)blockIdx.x * blockDim.x + threadIdx.x;  // float4 count
    if (idx >= (long long)BT * DFF / 4) return;
    float4 a = reinterpret_cast<float4*>(g1)[idx];
    float4 b = reinterpret_cast<const float4*>(g3)[idx];
    a.x = (a.x / (1.f + expf(-a.x))) * b.x;
    a.y = (a.y / (1.f + expf(-a.y))) * b.y;
    a.z = (a.z / (1.f + expf(-a.z))) * b.z;
    a.w = (a.w / (1.f + expf(-a.w))) * b.w;
    reinterpret_cast<float4*>(g1)[idx] = a;
}

// ---------------- host orchestration ----------------
static float* g_spPtr = nullptr;

static inline void launch_gemm(const float* A, const float* B, float* C,
                               int M, int N, int K, int lda, int ldb, int ldc,
                               long long sAb, long long sAh, long long sBb, long long sBh,
                               long long sCb, long long sCh, int Hbat, int nbat, int beta,
                               int splitS)
{
    dim3 grid((N + BN - 1) / BN, (M + BM - 1) / BM, nbat * splitS);
    gemm_tc<<<grid, NTHR>>>(A, B, C, M, N, K, lda, ldb, ldc,
                            sAb, sAh, sBb, sBh, sCb, sCh, Hbat, beta,
                            nbat, splitS, g_spPtr);
    if (splitS > 1) {
        // C footprint for all split-K call sites is exactly BT*Dm dense floats.
        reduce_k<<<(int)((SPCAP / 4 + 255) / 256), 256>>>(C, g_spPtr, splitS - 1);
    }
}

extern "C" void kernel_launch(void* const* d_in, const int* in_sizes, int n_in,
                              void* d_out, int out_size)
{
    const int*   tok         = (const int*)d_in[0];
    const int*   pos         = (const int*)d_in[1];
    const float* embed       = (const float*)d_in[2];
    const float* attn_norm_w = (const float*)d_in[3];
    const float* wq          = (const float*)d_in[4];
    const float* wk          = (const float*)d_in[5];
    const float* wv          = (const float*)d_in[6];
    const float* wo          = (const float*)d_in[7];
    const float* ff_norm_w   = (const float*)d_in[8];
    const float* w1          = (const float*)d_in[9];
    const float* w2          = (const float*)d_in[10];
    const float* w3          = (const float*)d_in[11];
    const float* norm_w      = (const float*)d_in[12];
    float* out = (float*)d_out;

    float *x, *h, *q, *k, *v, *vT, *o, *sc, *g1, *g3, *ct, *st;
    cudaGetSymbolAddress((void**)&x,  g_x);
    cudaGetSymbolAddress((void**)&h,  g_h);
    cudaGetSymbolAddress((void**)&q,  g_q);
    cudaGetSymbolAddress((void**)&k,  g_k);
    cudaGetSymbolAddress((void**)&v,  g_v);
    cudaGetSymbolAddress((void**)&vT, g_vT);
    cudaGetSymbolAddress((void**)&o,  g_o);
    cudaGetSymbolAddress((void**)&sc, g_sc);
    cudaGetSymbolAddress((void**)&g1, g_g1);
    cudaGetSymbolAddress((void**)&g3, g_g3);
    cudaGetSymbolAddress((void**)&ct, g_cos);
    cudaGetSymbolAddress((void**)&st, g_sin);
    cudaGetSymbolAddress((void**)&g_spPtr, g_sp);

    gather_k<<<BT, 256>>>(tok, embed, x);
    rope_tables_k<<<(BT * 32 + 255) / 256, 256>>>(pos, ct, st);

    const long long DD = (long long)Dm * Dm;
    for (int l = 0; l < Ll; l++) {
        // ---- attention ----
        rmsnorm_k<<<BT, 256>>>(x, attn_norm_w + (long long)l * Dm, h);
        launch_gemm(h, wq + l * DD, q, BT, Dm, Dm, Dm, Dm, Dm, 0,0,0,0,0,0, 1, 1, 0, 2);
        launch_gemm(h, wk + l * DD, k, BT, Dm, Dm, Dm, Dm, Dm, 0,0,0,0,0,0, 1, 1, 0, 2);
        launch_gemm(h, wv + l * DD, v, BT, Dm, Dm, Dm, Dm, Dm, 0,0,0,0,0,0, 1, 1, 0, 2);
        rope_apply_k<<<(BT * Hh * 32 + 255) / 256, 256>>>(q, ct, st);
        rope_apply_k<<<(BT * Hh * 32 + 255) / 256, 256>>>(k, ct, st);
        transpose_v_k<<<(BT * Dm + 255) / 256, 256>>>(v, vT);
        // scores[b,h,t,s] = q . k  (batched over 32 (b,h), K=64: no split)
        launch_gemm(q, k, sc, Tn, Tn, HDd, Dm, Dm, Tn,
                    (long long)Tn * Dm, HDd, (long long)Tn * Dm, HDd,
                    (long long)Hh * Tn * Tn, (long long)Tn * Tn, Hh, Bb * Hh, 0, 1);
        softmax_k<<<Bb * Hh * Tn, 256>>>(sc);
        // o[b,t,h,hd] = scores . vT  (split-K 2: grid 512 -> 1024)
        launch_gemm(sc, vT, o, Tn, HDd, Tn, Tn, Tn, Dm,
                    (long long)Hh * Tn * Tn, (long long)Tn * Tn,
                    (long long)Hh * HDd * Tn, (long long)HDd * Tn,
                    (long long)Tn * Dm, HDd, Hh, Bb * Hh, 0, 2);
        // x += o * wo^T
        launch_gemm(o, wo + l * DD, x, BT, Dm, Dm, Dm, Dm, Dm, 0,0,0,0,0,0, 1, 1, 1, 2);
        // ---- SwiGLU FFN ----
        rmsnorm_k<<<BT, 256>>>(x, ff_norm_w + (long long)l * Dm, h);
        launch_gemm(h, w1 + (long long)l * DFF * Dm, g1, BT, DFF, Dm, Dm, Dm, DFF, 0,0,0,0,0,0, 1, 1, 0, 1);
        launch_gemm(h, w3 + (long long)l * DFF * Dm, g3, BT, DFF, Dm, Dm, Dm, DFF, 0,0,0,0,0,0, 1, 1, 0, 1);
        silu_mul_k<<<(BT * DFF / 4 + 255) / 256, 256>>>(g1, g3);
        // x += g1 * w2^T  (K=4096: split-K 4 -> grid 1024)
        launch_gemm(g1, w2 + (long long)l * Dm * DFF, x, BT, Dm, DFF, DFF, DFF, Dm, 0,0,0,0,0,0, 1, 1, 1, 4);
    }

    // ---- final norm + tied LM head ----
    rmsnorm_k<<<BT, 256>>>(x, norm_w, h);
    launch_gemm(h, embed, out, BT, VOCAB, Dm, Dm, Dm, VOCAB, 0,0,0,0,0,0, 1, 1, 0, 1);
}